// round 1
// baseline (speedup 1.0000x reference)
#include <cuda_runtime.h>

// ODEFuncNN3Layer: out[B,2] = tanh(y[B,2] @ W1[50,2]^T + b1) @ W2[2,50]^T + b2
// Inputs (metadata order): t (scalar, unused), y, W1, b1, W2, b2.

constexpr int HID = 50;
constexpr int RPT = 4;     // rows per thread
constexpr int TPB = 256;   // threads per block

__device__ __forceinline__ float tanh_fast(float x) {
    float r;
    asm("tanh.approx.f32 %0, %1;" : "=f"(r) : "f"(x));
    return r;
}

__global__ __launch_bounds__(TPB) void ode_mlp_kernel(
    const float* __restrict__ y,
    const float* __restrict__ W1,   // [HID, 2] row-major
    const float* __restrict__ b1,   // [HID]
    const float* __restrict__ W2,   // [2, HID] row-major
    const float* __restrict__ b2,   // [2]
    float* __restrict__ out,
    int B)
{
    // Packed weights: per hidden unit j -> {W1[j][0], W1[j][1], W2[0][j], W2[1][j]}
    __shared__ float4 sw[HID];
    __shared__ float  sb1[HID];

    const int tid = threadIdx.x;
    if (tid < HID) {
        sw[tid]  = make_float4(W1[2 * tid], W1[2 * tid + 1], W2[tid], W2[HID + tid]);
        sb1[tid] = b1[tid];
    }
    const float c0 = b2[0];   // uniform; L1-cached broadcast
    const float c1 = b2[1];
    __syncthreads();

    const long base = ((long)(blockIdx.x * blockDim.x + tid)) * RPT;
    if (base >= B) return;

    if (base + RPT <= B) {
        // Fast path: 4 rows, fully vectorized 16B loads/stores.
        const float4 p0 = *(const float4*)(y + 2 * base);
        const float4 p1 = *(const float4*)(y + 2 * base + 4);
        float y0[RPT] = {p0.x, p0.z, p1.x, p1.z};
        float y1[RPT] = {p0.y, p0.w, p1.y, p1.w};
        float o0[RPT], o1[RPT];
        #pragma unroll
        for (int r = 0; r < RPT; r++) { o0[r] = c0; o1[r] = c1; }

        #pragma unroll
        for (int j = 0; j < HID; j++) {
            const float4 w  = sw[j];
            const float  bj = sb1[j];
            #pragma unroll
            for (int r = 0; r < RPT; r++) {
                const float pre = fmaf(y0[r], w.x, fmaf(y1[r], w.y, bj));
                const float h   = tanh_fast(pre);
                o0[r] = fmaf(h, w.z, o0[r]);
                o1[r] = fmaf(h, w.w, o1[r]);
            }
        }

        *(float4*)(out + 2 * base)     = make_float4(o0[0], o1[0], o0[1], o1[1]);
        *(float4*)(out + 2 * base + 4) = make_float4(o0[2], o1[2], o0[3], o1[3]);
    } else {
        // Tail path: per-row scalar with guard.
        for (long row = base; row < B; row++) {
            const float a0 = y[2 * row], a1 = y[2 * row + 1];
            float o0 = c0, o1 = c1;
            #pragma unroll
            for (int j = 0; j < HID; j++) {
                const float4 w = sw[j];
                const float h  = tanh_fast(fmaf(a0, w.x, fmaf(a1, w.y, sb1[j])));
                o0 = fmaf(h, w.z, o0);
                o1 = fmaf(h, w.w, o1);
            }
            out[2 * row]     = o0;
            out[2 * row + 1] = o1;
        }
    }
}

extern "C" void kernel_launch(void* const* d_in, const int* in_sizes, int n_in,
                              void* d_out, int out_size) {
    // metadata order: t, y, W1, b1, W2, b2
    const float* y  = (const float*)d_in[1];
    const float* W1 = (const float*)d_in[2];
    const float* b1 = (const float*)d_in[3];
    const float* W2 = (const float*)d_in[4];
    const float* b2 = (const float*)d_in[5];
    float* out = (float*)d_out;

    const int B = in_sizes[1] / 2;
    const int rows_per_block = TPB * RPT;
    const int blocks = (B + rows_per_block - 1) / rows_per_block;
    ode_mlp_kernel<<<blocks, TPB>>>(y, W1, b1, W2, b2, out, B);
}

// round 2
// speedup vs baseline: 1.4503x; 1.4503x over previous
#include <cuda_runtime.h>

// ODEFuncNN3Layer: out[B,2] = tanh(y[B,2] @ W1[50,2]^T + b1) @ W2[2,50]^T + b2
// Inputs (metadata order): t (scalar, unused), y, W1, b1, W2, b2.

constexpr int HID = 50;
constexpr int RPT = 4;     // rows per thread
constexpr int TPB = 256;   // threads per block

__device__ __forceinline__ float tanh_fast(float x) {
    float r;
    asm("tanh.approx.f32 %0, %1;" : "=f"(r) : "f"(x));
    return r;
}

__global__ __launch_bounds__(TPB, 4) void ode_mlp_kernel(
    const float* __restrict__ y,
    const float* __restrict__ W1,   // [HID, 2] row-major
    const float* __restrict__ b1,   // [HID]
    const float* __restrict__ W2,   // [2, HID] row-major
    const float* __restrict__ b2,   // [2]
    float* __restrict__ out,
    int B)
{
    // Packed weights: per hidden unit j -> {W1[j][0], W1[j][1], W2[0][j], W2[1][j]}
    __shared__ float4 sw[HID];
    __shared__ float  sb1[HID];

    const int tid = threadIdx.x;
    if (tid < HID) {
        sw[tid]  = make_float4(W1[2 * tid], W1[2 * tid + 1], W2[tid], W2[HID + tid]);
        sb1[tid] = b1[tid];
    }
    const float c0 = b2[0];   // uniform; L1-cached broadcast
    const float c1 = b2[1];
    __syncthreads();

    const long base = ((long)(blockIdx.x * blockDim.x + tid)) * RPT;
    if (base >= B) return;

    if (base + RPT <= B) {
        // Fast path: 4 rows, fully vectorized 16B loads/stores.
        const float4 p0 = *(const float4*)(y + 2 * base);
        const float4 p1 = *(const float4*)(y + 2 * base + 4);
        float y0[RPT] = {p0.x, p0.z, p1.x, p1.z};
        float y1[RPT] = {p0.y, p0.w, p1.y, p1.w};
        float o0[RPT], o1[RPT];
        #pragma unroll
        for (int r = 0; r < RPT; r++) { o0[r] = c0; o1[r] = c1; }

        // Partial unroll: keeps live weight registers bounded (ptxas at full
        // unroll front-batches all 50 LDS.128 -> 255 regs -> occupancy 1 CTA/SM).
        #pragma unroll 5
        for (int j = 0; j < HID; j++) {
            const float4 w  = sw[j];
            const float  bj = sb1[j];
            #pragma unroll
            for (int r = 0; r < RPT; r++) {
                const float pre = fmaf(y0[r], w.x, fmaf(y1[r], w.y, bj));
                const float h   = tanh_fast(pre);
                o0[r] = fmaf(h, w.z, o0[r]);
                o1[r] = fmaf(h, w.w, o1[r]);
            }
        }

        *(float4*)(out + 2 * base)     = make_float4(o0[0], o1[0], o0[1], o1[1]);
        *(float4*)(out + 2 * base + 4) = make_float4(o0[2], o1[2], o0[3], o1[3]);
    } else {
        // Tail path: per-row scalar with guard.
        for (long row = base; row < B; row++) {
            const float a0 = y[2 * row], a1 = y[2 * row + 1];
            float o0 = c0, o1 = c1;
            #pragma unroll 5
            for (int j = 0; j < HID; j++) {
                const float4 w = sw[j];
                const float h  = tanh_fast(fmaf(a0, w.x, fmaf(a1, w.y, sb1[j])));
                o0 = fmaf(h, w.z, o0);
                o1 = fmaf(h, w.w, o1);
            }
            out[2 * row]     = o0;
            out[2 * row + 1] = o1;
        }
    }
}

extern "C" void kernel_launch(void* const* d_in, const int* in_sizes, int n_in,
                              void* d_out, int out_size) {
    // metadata order: t, y, W1, b1, W2, b2
    const float* y  = (const float*)d_in[1];
    const float* W1 = (const float*)d_in[2];
    const float* b1 = (const float*)d_in[3];
    const float* W2 = (const float*)d_in[4];
    const float* b2 = (const float*)d_in[5];
    float* out = (float*)d_out;

    const int B = in_sizes[1] / 2;
    const int rows_per_block = TPB * RPT;
    const int blocks = (B + rows_per_block - 1) / rows_per_block;
    ode_mlp_kernel<<<blocks, TPB>>>(y, W1, b1, W2, b2, out, B);
}